// round 1
// baseline (speedup 1.0000x reference)
#include <cuda_runtime.h>
#include <cuda_bf16.h>
#include <cstdint>

// Conv2D: x[8,16,512,512] * w[16,16,3,3] -> out[8,16,512,512], stride 1, pad 1.
//
// Strategy: smem-tiled direct conv, f32x2 packed FMA (FFMA2) for full-rate fp32.
// Block tile: 32x(x) * 16(y) outputs, all 16 c_out, one image.
// Threads: 256 = 4 co-groups x 2 y-groups x 32 lanes (lane = x).
// Each thread: 8 y-pixels x 4 c_out = 16 f32x2 accumulators (paired over c_out).

#define TILE_X 32
#define TILE_Y 16
#define IN_TX  34   // TILE_X + 2 halo
#define IN_TY  18   // TILE_Y + 2 halo
#define C 16
#define HW 512

static __device__ __forceinline__ unsigned long long pack2(float a, float b) {
    unsigned long long r;
    asm("mov.b64 %0, {%1, %2};" : "=l"(r) : "f"(a), "f"(b));
    return r;
}
static __device__ __forceinline__ unsigned long long fma2(unsigned long long a,
                                                          unsigned long long b,
                                                          unsigned long long c) {
    unsigned long long d;
    asm("fma.rn.f32x2 %0, %1, %2, %3;" : "=l"(d) : "l"(a), "l"(b), "l"(c));
    return d;
}
static __device__ __forceinline__ void unpack2(unsigned long long v, float& lo, float& hi) {
    asm("mov.b64 {%0, %1}, %2;" : "=f"(lo), "=f"(hi) : "l"(v));
}

__global__ __launch_bounds__(256, 2)
void conv3x3_kernel(const float* __restrict__ x,
                    const float* __restrict__ weight,
                    float* __restrict__ out) {
    // smem: input tile [ci][ly][lx], weights repacked [ci][k][co]
    __shared__ __align__(16) float in_s[C * IN_TY * IN_TX];   // 16*18*34*4 = 39168 B
    __shared__ __align__(16) float w_s[C * 9 * C];            // 16*9*16*4  =  9216 B

    const int t    = threadIdx.x;
    const int lane = t & 31;
    const int warp = t >> 5;
    const int g    = warp & 3;   // co-group: couts 4g..4g+3
    const int yg   = warp >> 2;  // y-group: rows yg*8..yg*8+7 of the 16-row tile

    const int bx = blockIdx.x;   // 16 tiles of 32 in x
    const int by = blockIdx.y;   // 32 tiles of 16 in y
    const int n  = blockIdx.z;   // 8 images

    // ---- load input tile (zero-padded halo) ----
    const int x0 = bx * TILE_X - 1;
    const int y0 = by * TILE_Y - 1;
    #pragma unroll 1
    for (int idx = t; idx < C * IN_TY * IN_TX; idx += 256) {
        int ci  = idx / (IN_TY * IN_TX);
        int rem = idx - ci * (IN_TY * IN_TX);
        int ly  = rem / IN_TX;
        int lx  = rem - ly * IN_TX;
        int gy = y0 + ly;
        int gx = x0 + lx;
        float v = 0.0f;
        if ((unsigned)gy < HW && (unsigned)gx < HW)
            v = x[(((size_t)n * C + ci) * HW + gy) * HW + gx];
        in_s[idx] = v;
    }

    // ---- repack weights: w_s[ci][k][co] = weight[co*144 + ci*9 + k] ----
    #pragma unroll 1
    for (int idx = t; idx < C * 9 * C; idx += 256) {
        int co = idx & 15;
        int k  = (idx >> 4) % 9;
        int ci = idx / 144;
        w_s[idx] = weight[co * 144 + ci * 9 + k];
    }
    __syncthreads();

    // ---- main loop ----
    unsigned long long acc[8][2];
    #pragma unroll
    for (int yy = 0; yy < 8; ++yy) { acc[yy][0] = 0ull; acc[yy][1] = 0ull; }

    #pragma unroll 2
    for (int ci = 0; ci < C; ++ci) {
        const float* ib = in_s + ci * (IN_TY * IN_TX) + yg * (8 * IN_TX) + lane;
        const float* wb = w_s + ci * 144 + g * 4;

        #pragma unroll
        for (int kw = 0; kw < 3; ++kw) {
            // column of 10 input values (y halo included), packed (v,v) once,
            // reused across the 3 kh taps
            unsigned long long p[10];
            #pragma unroll
            for (int j = 0; j < 10; ++j) {
                float v = ib[j * IN_TX + kw];
                p[j] = pack2(v, v);
            }
            #pragma unroll
            for (int kh = 0; kh < 3; ++kh) {
                const double* wp = reinterpret_cast<const double*>(wb + (kh * 3 + kw) * 16);
                unsigned long long wlo = __double_as_longlong(wp[0]);  // (w[4g],   w[4g+1])
                unsigned long long whi = __double_as_longlong(wp[1]);  // (w[4g+2], w[4g+3])
                #pragma unroll
                for (int yy = 0; yy < 8; ++yy) {
                    acc[yy][0] = fma2(wlo, p[yy + kh], acc[yy][0]);
                    acc[yy][1] = fma2(whi, p[yy + kh], acc[yy][1]);
                }
            }
        }
    }

    // ---- store ----
    const int oy0 = by * TILE_Y + yg * 8;
    const int ox  = bx * TILE_X + lane;
    const int co0 = g * 4;
    #pragma unroll
    for (int yy = 0; yy < 8; ++yy) {
        #pragma unroll
        for (int pp = 0; pp < 2; ++pp) {
            float lo, hi;
            unpack2(acc[yy][pp], lo, hi);
            size_t base = (((size_t)n * C + (co0 + 2 * pp)) * HW + (oy0 + yy)) * HW + ox;
            out[base] = lo;
            out[base + (size_t)HW * HW] = hi;
        }
    }
}

extern "C" void kernel_launch(void* const* d_in, const int* in_sizes, int n_in,
                              void* d_out, int out_size) {
    const float* x = (const float*)d_in[0];       // [8,16,512,512]
    const float* w = (const float*)d_in[1];       // [16, 144]
    float* out = (float*)d_out;                   // [8,16,512,512]

    dim3 grid(HW / TILE_X, HW / TILE_Y, 8);       // (16, 32, 8)
    conv3x3_kernel<<<grid, 256>>>(x, w, out);
}

// round 3
// speedup vs baseline: 2.2064x; 2.2064x over previous
#include <cuda_runtime.h>
#include <cuda_fp16.h>
#include <cstdint>

// Conv2D 3x3 s1 p1: x[8,16,512,512] fp32 * w[16,144] -> out[8,16,512,512]
// Implicit GEMM on mma.sync.m16n8k16 (f16 in, f32 acc).
// D[pixels(M), co(N)] = sum_kh A_kh[pixels, k=kw*16+ci] * B_kh[co, k]
// A is never materialized: staged tile ns[yy][xx][ci] IS A under this k-order;
// kh handled by yy shift, kw by xx shift, K=48 = 3 exact k16 steps.
// CTA: 32(x) x 16(y) pixels, all 16 co. 8 warps x 4 m16-tiles (m=(y,xhalf)).

#define HW   512
#define NSX  34
#define NSY  18
#define CPAD 24    // ci stride in halves -> 48B rows (16B aligned, conflict-free frags)

static __device__ __forceinline__ void mma16816(float* c, uint32_t a0, uint32_t a1,
                                                uint32_t a2, uint32_t a3,
                                                uint32_t b0, uint32_t b1) {
    asm volatile(
        "mma.sync.aligned.m16n8k16.row.col.f32.f16.f16.f32 "
        "{%0,%1,%2,%3}, {%4,%5,%6,%7}, {%8,%9}, {%0,%1,%2,%3};"
        : "+f"(c[0]), "+f"(c[1]), "+f"(c[2]), "+f"(c[3])
        : "r"(a0), "r"(a1), "r"(a2), "r"(a3), "r"(b0), "r"(b1));
}

__global__ __launch_bounds__(256, 3)
void conv_mma_kernel(const float* __restrict__ xin,
                     const float* __restrict__ wgt,
                     float* __restrict__ out)
{
    __shared__ __align__(16) __half ns[NSY * NSX * CPAD];  // 29376 B
    __shared__ __align__(16) __half Bs[3 * 16 * 48];       //  4608 B: [kh][co][kw*16+ci]

    const int t    = threadIdx.x;
    const int lane = t & 31;
    const int wrp  = t >> 5;
    const int x0 = blockIdx.x * 32;
    const int y0 = blockIdx.y * 16;
    const int n  = blockIdx.z;

    // ---- stage input tile (fp32 -> fp16), layout [yy][xx][ci] ----
    #pragma unroll 1
    for (int idx = t; idx < 16 * NSY * NSX; idx += 256) {
        int ci  = idx / (NSY * NSX);
        int rem = idx - ci * (NSY * NSX);
        int yy  = rem / NSX;
        int xx  = rem - yy * NSX;
        int gy = y0 + yy - 1, gx = x0 + xx - 1;
        float v = 0.0f;
        if ((unsigned)gy < HW && (unsigned)gx < HW)
            v = xin[(((size_t)(n * 16 + ci)) * HW + gy) * HW + gx];
        ns[(yy * NSX + xx) * CPAD + ci] = __float2half_rn(v);
    }
    // ---- stage weights: Bs[kh][co][kw*16+ci] ----
    #pragma unroll 1
    for (int idx = t; idx < 3 * 16 * 48; idx += 256) {
        int kh  = idx / 768;
        int rem = idx - kh * 768;
        int co  = rem / 48;
        int k   = rem - co * 48;
        int kw = k >> 4, ci = k & 15;
        Bs[idx] = __float2half_rn(wgt[co * 144 + ci * 9 + kh * 3 + kw]);
    }
    __syncthreads();

    float acc[4][2][4];
    #pragma unroll
    for (int i = 0; i < 4; ++i)
        #pragma unroll
        for (int nn = 0; nn < 2; ++nn)
            #pragma unroll
            for (int j = 0; j < 4; ++j) acc[i][nn][j] = 0.0f;

    const int g  = lane >> 2;        // M row / N col group
    const int cq = (lane & 3) * 2;   // k-pair base (= ci pair)

    #pragma unroll
    for (int dy = 0; dy < 3; ++dy) {
        // B fragments for this kh: 12 regs
        uint32_t bf[3][2][2];
        #pragma unroll
        for (int kw = 0; kw < 3; ++kw)
            #pragma unroll
            for (int nn = 0; nn < 2; ++nn) {
                const __half* bp = &Bs[(dy * 16 + nn * 8 + g) * 48 + kw * 16 + cq];
                bf[kw][nn][0] = *(const uint32_t*)bp;        // k = cq, cq+1
                bf[kw][nn][1] = *(const uint32_t*)(bp + 8);  // k = cq+8, cq+9
            }
        #pragma unroll
        for (int i = 0; i < 4; ++i) {
            const int m    = wrp * 4 + i;
            const int yloc = m >> 1;
            const int xh   = m & 1;
            const int yy   = yloc + dy;
            #pragma unroll
            for (int kw = 0; kw < 3; ++kw) {
                const __half* ap = &ns[(yy * NSX + xh * 16 + g + kw) * CPAD + cq];
                uint32_t a0 = *(const uint32_t*)ap;                  // row g,   ci cq..cq+1
                uint32_t a1 = *(const uint32_t*)(ap + 8 * CPAD);     // row g+8
                uint32_t a2 = *(const uint32_t*)(ap + 8);            // ci +8
                uint32_t a3 = *(const uint32_t*)(ap + 8 * CPAD + 8);
                mma16816(acc[i][0], a0, a1, a2, a3, bf[kw][0][0], bf[kw][0][1]);
                mma16816(acc[i][1], a0, a1, a2, a3, bf[kw][1][0], bf[kw][1][1]);
            }
        }
    }

    // ---- epilogue: direct stores ----
    #pragma unroll
    for (int i = 0; i < 4; ++i) {
        const int m    = wrp * 4 + i;
        const int yloc = m >> 1;
        const int xh   = m & 1;
        const int y  = y0 + yloc;
        const int xb = x0 + xh * 16 + g;
        #pragma unroll
        for (int nn = 0; nn < 2; ++nn) {
            const int co = nn * 8 + cq;
            float* op = out + ((size_t)(n * 16 + co) * HW + y) * HW + xb;
            op[0]                   = acc[i][nn][0];  // (x,   co)
            op[(size_t)HW * HW]     = acc[i][nn][1];  // (x,   co+1)
            op[8]                   = acc[i][nn][2];  // (x+8, co)
            op[(size_t)HW * HW + 8] = acc[i][nn][3];  // (x+8, co+1)
        }
    }
}

extern "C" void kernel_launch(void* const* d_in, const int* in_sizes, int n_in,
                              void* d_out, int out_size) {
    const float* x = (const float*)d_in[0];   // [8,16,512,512]
    const float* w = (const float*)d_in[1];   // [16,144]
    float* out = (float*)d_out;

    dim3 grid(HW / 32, HW / 16, 8);           // (16, 32, 8)
    conv_mma_kernel<<<grid, 256>>>(x, w, out);
}

// round 4
// speedup vs baseline: 3.7947x; 1.7198x over previous
#include <cuda_runtime.h>
#include <cuda_fp16.h>
#include <cstdint>

// Conv2D 3x3 s1 p1: x[8,16,512,512] fp32 * w[16,144] -> out[8,16,512,512]
// Implicit GEMM on mma.sync.m16n8k16 (f16 in, f32 acc).
// D[pixels(M), co(N)] = sum_kh A_kh[pixels, k=kw*16+ci] * B_kh[co, k]
// A never materialized: staged tile ns[yy][xx][ci] IS A under this k-order.
// CTA: 32(x) x 16(y) pixels, all 16 co. 8 warps x 4 m16-tiles.
// R4: staging rebuilt — div-free thread mapping, batched loads (MLP ~8).

#define HW   512
#define NSX  34
#define NSY  18
#define CPAD 24    // ci stride in halves -> 48B rows, conflict-free frag LDS

static __device__ __forceinline__ void mma16816(float* c, uint32_t a0, uint32_t a1,
                                                uint32_t a2, uint32_t a3,
                                                uint32_t b0, uint32_t b1) {
    asm volatile(
        "mma.sync.aligned.m16n8k16.row.col.f32.f16.f16.f32 "
        "{%0,%1,%2,%3}, {%4,%5,%6,%7}, {%8,%9}, {%0,%1,%2,%3};"
        : "+f"(c[0]), "+f"(c[1]), "+f"(c[2]), "+f"(c[3])
        : "r"(a0), "r"(a1), "r"(a2), "r"(a3), "r"(b0), "r"(b1));
}

__global__ __launch_bounds__(256, 3)
void conv_mma_kernel(const float* __restrict__ xin,
                     const float* __restrict__ wgt,
                     float* __restrict__ out)
{
    __shared__ __align__(16) __half ns[NSY * NSX * CPAD];  // 29376 B
    __shared__ __align__(16) __half Bs[3 * 16 * 48];       //  4608 B: [kh][co][kw*16+ci]

    const int t    = threadIdx.x;
    const int lane = t & 31;
    const int wrp  = t >> 5;
    const int x0 = blockIdx.x * 32;
    const int y0 = blockIdx.y * 16;
    const int n  = blockIdx.z;

    // ---- stage input tile (fp32 -> fp16), layout ns[yy][xx][ci] ----
    // thread = (ci = t>>4, xb = t&15); columns xx in {xb, xb+16, 32+xb (xb<2)}.
    {
        const int ci = t >> 4;
        const int xb = t & 15;
        const int gxA = x0 + xb - 1;
        const int gxB = gxA + 16;
        const int gxC = x0 + 31 + xb;          // xx = 32+xb
        const bool pA = (unsigned)gxA < HW;    // false only at left image edge
        const bool hasC = (xb < 2);
        const bool pC = hasC && ((unsigned)gxC < HW);

        const float* src = xin + ((size_t)(n * 16 + ci)) * HW * HW;
        __half* dst = ns + ci;

        #pragma unroll 3
        for (int yy = 0; yy < NSY; ++yy) {
            const int gy = y0 + yy - 1;
            const bool pY = (unsigned)gy < HW;
            const float* row = src + (size_t)gy * HW;
            float vA = 0.f, vB = 0.f, vC = 0.f;
            if (pY) {
                if (pA) vA = row[gxA];
                vB = row[gxB];                 // always in range
                if (pC) vC = row[gxC];
            }
            __half* d = dst + (yy * NSX) * CPAD;
            d[(xb)      * CPAD] = __float2half_rn(vA);
            d[(xb + 16) * CPAD] = __float2half_rn(vB);
            if (hasC) d[(32 + xb) * CPAD] = __float2half_rn(vC);
        }
    }
    // ---- stage weights: Bs[kh][co][kw*16+ci]  (2304 elems, 9/thread) ----
    #pragma unroll
    for (int r = 0; r < 9; ++r) {
        int idx = t + r * 256;
        int kh  = idx / 768;
        int rem = idx - kh * 768;
        int co  = rem / 48;
        int k   = rem - co * 48;
        int kw = k >> 4, ci = k & 15;
        Bs[idx] = __float2half_rn(wgt[co * 144 + ci * 9 + kh * 3 + kw]);
    }
    __syncthreads();

    float acc[4][2][4];
    #pragma unroll
    for (int i = 0; i < 4; ++i)
        #pragma unroll
        for (int nn = 0; nn < 2; ++nn)
            #pragma unroll
            for (int j = 0; j < 4; ++j) acc[i][nn][j] = 0.0f;

    const int g  = lane >> 2;        // M row / N col group
    const int cq = (lane & 3) * 2;   // k-pair base (= ci pair)

    #pragma unroll
    for (int dy = 0; dy < 3; ++dy) {
        uint32_t bf[3][2][2];
        #pragma unroll
        for (int kw = 0; kw < 3; ++kw)
            #pragma unroll
            for (int nn = 0; nn < 2; ++nn) {
                const __half* bp = &Bs[(dy * 16 + nn * 8 + g) * 48 + kw * 16 + cq];
                bf[kw][nn][0] = *(const uint32_t*)bp;
                bf[kw][nn][1] = *(const uint32_t*)(bp + 8);
            }
        #pragma unroll
        for (int i = 0; i < 4; ++i) {
            const int m    = wrp * 4 + i;
            const int yloc = m >> 1;
            const int xh   = m & 1;
            const int yy   = yloc + dy;
            #pragma unroll
            for (int kw = 0; kw < 3; ++kw) {
                const __half* ap = &ns[(yy * NSX + xh * 16 + g + kw) * CPAD + cq];
                uint32_t a0 = *(const uint32_t*)ap;
                uint32_t a1 = *(const uint32_t*)(ap + 8 * CPAD);
                uint32_t a2 = *(const uint32_t*)(ap + 8);
                uint32_t a3 = *(const uint32_t*)(ap + 8 * CPAD + 8);
                mma16816(acc[i][0], a0, a1, a2, a3, bf[kw][0][0], bf[kw][0][1]);
                mma16816(acc[i][1], a0, a1, a2, a3, bf[kw][1][0], bf[kw][1][1]);
            }
        }
    }

    // ---- epilogue: direct stores ----
    #pragma unroll
    for (int i = 0; i < 4; ++i) {
        const int m    = wrp * 4 + i;
        const int yloc = m >> 1;
        const int xh   = m & 1;
        const int y  = y0 + yloc;
        const int xb = x0 + xh * 16 + g;
        #pragma unroll
        for (int nn = 0; nn < 2; ++nn) {
            const int co = nn * 8 + cq;
            float* op = out + ((size_t)(n * 16 + co) * HW + y) * HW + xb;
            op[0]                   = acc[i][nn][0];
            op[(size_t)HW * HW]     = acc[i][nn][1];
            op[8]                   = acc[i][nn][2];
            op[(size_t)HW * HW + 8] = acc[i][nn][3];
        }
    }
}

extern "C" void kernel_launch(void* const* d_in, const int* in_sizes, int n_in,
                              void* d_out, int out_size) {
    const float* x = (const float*)d_in[0];   // [8,16,512,512]
    const float* w = (const float*)d_in[1];   // [16,144]
    float* out = (float*)d_out;

    dim3 grid(HW / 32, HW / 16, 8);           // (16, 32, 8)
    conv_mma_kernel<<<grid, 256>>>(x, w, out);
}

// round 5
// speedup vs baseline: 4.3128x; 1.1365x over previous
#include <cuda_runtime.h>
#include <cuda_fp16.h>
#include <cstdint>

// Conv2D 3x3 s1 p1: x[8,16,512,512] fp32 * w[16,144] -> out[8,16,512,512]
// Implicit GEMM on mma.sync.m16n8k16 (f16, f32 acc), persistent CTAs with a
// depth-1 cp.async pipeline: tile k+1's fp32 halo streams into a raw smem
// buffer while tile k computes. cvt pass (own-bytes, no barrier) fills a
// double-buffered fp16 tile ns16[p]; one __syncthreads per tile.
// CTA tile: 32(x) x 16(y) pixels, all 16 co. 8 warps x 4 m16-tiles.

#define HW    512
#define NSX   34
#define NSY   18
#define CPAD  24        // ci stride (halves) -> 48B rows, conflict-free frags
#define NTILES 4096     // 16 x 32 x 8
#define GRID  304       // 2 CTAs/SM x 152 SMs, single wave

#define RAW_OFF 0                     // 16*18*34 fp32 = 39168 B
#define NS_OFF  39168                 // 2 x (18*34*24 fp16 = 29376 B)
#define NS_SZ   29376
#define BS_OFF  97920                 // 3*16*48 fp16 = 4608 B
#define SM_TOTAL 102528

static __device__ __forceinline__ void mma16816(float* c, uint32_t a0, uint32_t a1,
                                                uint32_t a2, uint32_t a3,
                                                uint32_t b0, uint32_t b1) {
    asm volatile(
        "mma.sync.aligned.m16n8k16.row.col.f32.f16.f16.f32 "
        "{%0,%1,%2,%3}, {%4,%5,%6,%7}, {%8,%9}, {%0,%1,%2,%3};"
        : "+f"(c[0]), "+f"(c[1]), "+f"(c[2]), "+f"(c[3])
        : "r"(a0), "r"(a1), "r"(a2), "r"(a3), "r"(b0), "r"(b1));
}

static __device__ __forceinline__ void cp4(uint32_t daddr, const float* src, uint32_t sz) {
    // cp-size 4, src-size sz (0 -> zero-fill). Padding handled by zfill.
    asm volatile("cp.async.ca.shared.global [%0], [%1], 4, %2;"
                 :: "r"(daddr), "l"(src), "r"(sz) : "memory");
}

static __device__ __forceinline__ uint32_t smem_u32(const void* p) {
    uint32_t a;
    asm("{ .reg .u64 t; cvta.to.shared.u64 t, %1; cvt.u32.u64 %0, t; }" : "=r"(a) : "l"(p));
    return a;
}

__global__ __launch_bounds__(256, 2)
void conv_mma_pipe(const float* __restrict__ xin,
                   const float* __restrict__ wgt,
                   float* __restrict__ out)
{
    extern __shared__ __align__(16) char smem[];
    float*  raw = (float*)(smem + RAW_OFF);
    __half* Bs  = (__half*)(smem + BS_OFF);
    const uint32_t sraw = smem_u32(smem) + RAW_OFF;

    const int t    = threadIdx.x;
    const int lane = t & 31;
    const int wrp  = t >> 5;
    const int ci   = t >> 4;     // staging/cvt mapping
    const int xb   = t & 15;
    const bool hasC = (xb < 2);

    // ---- stage weights once: Bs[kh][co][kw*16+ci] ----
    #pragma unroll
    for (int r = 0; r < 9; ++r) {
        int idx = t + r * 256;
        int kh  = idx / 768;
        int rem = idx - kh * 768;
        int co  = rem / 48;
        int k   = rem - co * 48;
        Bs[idx] = __float2half_rn(wgt[co * 144 + (k & 15) * 9 + kh * 3 + (k >> 4)]);
    }

    const int g  = lane >> 2;
    const int cq = (lane & 3) * 2;

    // ---- issue cp.async for first tile ----
    {
        const int tile = blockIdx.x;
        const int x0 = (tile & 15) * 32, y0 = ((tile >> 4) & 31) * 16, n = tile >> 9;
        const float* src = xin + (size_t)(n * 16 + ci) * HW * HW;
        const int gxA = x0 + xb - 1, gxB = gxA + 16, gxC = x0 + 31 + xb;
        const bool okA = (unsigned)gxA < HW;
        const bool okC = hasC && ((unsigned)gxC < HW);
        const uint32_t d0 = sraw + (uint32_t)(ci * 612) * 4;
        #pragma unroll 3
        for (int yy = 0; yy < NSY; ++yy) {
            const int gy = y0 + yy - 1;
            const bool okY = (unsigned)gy < HW;
            const float* row = src + (size_t)(okY ? gy : 0) * HW;
            const uint32_t dd = d0 + (uint32_t)(yy * 136);
            cp4(dd + xb * 4,        row + (okA ? gxA : 0), (okY && okA) ? 4u : 0u);
            cp4(dd + (xb + 16) * 4, row + gxB,             okY ? 4u : 0u);
            if (hasC)
                cp4(dd + (32 + xb) * 4, row + (okC ? gxC : 0), (okY && okC) ? 4u : 0u);
        }
        asm volatile("cp.async.commit_group;" ::: "memory");
    }

    int p = 0;
    for (int tile = blockIdx.x; tile < NTILES; tile += GRID) {
        const int x0 = (tile & 15) * 32, y0 = ((tile >> 4) & 31) * 16, n = tile >> 9;

        // ---- wait for this tile's raw data (own bytes only -> no barrier) ----
        asm volatile("cp.async.wait_group 0;" ::: "memory");

        // ---- cvt raw fp32 -> ns16[p] fp16 (own bytes) ----
        __half* ns = (__half*)(smem + NS_OFF + p * NS_SZ);
        {
            const float* rp = raw + ci * 612;
            __half* np = ns + ci;
            #pragma unroll 3
            for (int yy = 0; yy < NSY; ++yy) {
                const float* rr = rp + yy * 34;
                __half* dn = np + yy * (NSX * CPAD);
                dn[xb * CPAD]        = __float2half_rn(rr[xb]);
                dn[(xb + 16) * CPAD] = __float2half_rn(rr[xb + 16]);
                if (hasC)
                    dn[(32 + xb) * CPAD] = __float2half_rn(rr[32 + xb]);
            }
        }

        // ---- issue cp.async for next tile (overlaps with compute below) ----
        if (tile + GRID < NTILES) {
            const int tn = tile + GRID;
            const int nx0 = (tn & 15) * 32, ny0 = ((tn >> 4) & 31) * 16, nn = tn >> 9;
            const float* src = xin + (size_t)(nn * 16 + ci) * HW * HW;
            const int gxA = nx0 + xb - 1, gxB = gxA + 16, gxC = nx0 + 31 + xb;
            const bool okA = (unsigned)gxA < HW;
            const bool okC = hasC && ((unsigned)gxC < HW);
            const uint32_t d0 = sraw + (uint32_t)(ci * 612) * 4;
            #pragma unroll 3
            for (int yy = 0; yy < NSY; ++yy) {
                const int gy = ny0 + yy - 1;
                const bool okY = (unsigned)gy < HW;
                const float* row = src + (size_t)(okY ? gy : 0) * HW;
                const uint32_t dd = d0 + (uint32_t)(yy * 136);
                cp4(dd + xb * 4,        row + (okA ? gxA : 0), (okY && okA) ? 4u : 0u);
                cp4(dd + (xb + 16) * 4, row + gxB,             okY ? 4u : 0u);
                if (hasC)
                    cp4(dd + (32 + xb) * 4, row + (okC ? gxC : 0), (okY && okC) ? 4u : 0u);
            }
            asm volatile("cp.async.commit_group;" ::: "memory");
        }

        __syncthreads();   // ns16[p] visible to all; also fences buffer reuse

        // ---- compute (identical to R4 main loop) ----
        float acc[4][2][4];
        #pragma unroll
        for (int i = 0; i < 4; ++i)
            #pragma unroll
            for (int nn2 = 0; nn2 < 2; ++nn2)
                #pragma unroll
                for (int j = 0; j < 4; ++j) acc[i][nn2][j] = 0.0f;

        #pragma unroll
        for (int dy = 0; dy < 3; ++dy) {
            uint32_t bf[3][2][2];
            #pragma unroll
            for (int kw = 0; kw < 3; ++kw)
                #pragma unroll
                for (int nn2 = 0; nn2 < 2; ++nn2) {
                    const __half* bp = &Bs[(dy * 16 + nn2 * 8 + g) * 48 + kw * 16 + cq];
                    bf[kw][nn2][0] = *(const uint32_t*)bp;
                    bf[kw][nn2][1] = *(const uint32_t*)(bp + 8);
                }
            #pragma unroll
            for (int i = 0; i < 4; ++i) {
                const int m    = wrp * 4 + i;
                const int yloc = m >> 1;
                const int xh   = m & 1;
                const int yy   = yloc + dy;
                #pragma unroll
                for (int kw = 0; kw < 3; ++kw) {
                    const __half* ap = &ns[(yy * NSX + xh * 16 + g + kw) * CPAD + cq];
                    uint32_t a0 = *(const uint32_t*)ap;
                    uint32_t a1 = *(const uint32_t*)(ap + 8 * CPAD);
                    uint32_t a2 = *(const uint32_t*)(ap + 8);
                    uint32_t a3 = *(const uint32_t*)(ap + 8 * CPAD + 8);
                    mma16816(acc[i][0], a0, a1, a2, a3, bf[kw][0][0], bf[kw][0][1]);
                    mma16816(acc[i][1], a0, a1, a2, a3, bf[kw][1][0], bf[kw][1][1]);
                }
            }
        }

        // ---- epilogue ----
        #pragma unroll
        for (int i = 0; i < 4; ++i) {
            const int m    = wrp * 4 + i;
            const int yloc = m >> 1;
            const int xh   = m & 1;
            const int y  = y0 + yloc;
            const int xg = x0 + xh * 16 + g;
            #pragma unroll
            for (int nn2 = 0; nn2 < 2; ++nn2) {
                const int co = nn2 * 8 + cq;
                float* op = out + ((size_t)(n * 16 + co) * HW + y) * HW + xg;
                op[0]                   = acc[i][nn2][0];
                op[(size_t)HW * HW]     = acc[i][nn2][1];
                op[8]                   = acc[i][nn2][2];
                op[(size_t)HW * HW + 8] = acc[i][nn2][3];
            }
        }

        p ^= 1;
    }
}

extern "C" void kernel_launch(void* const* d_in, const int* in_sizes, int n_in,
                              void* d_out, int out_size) {
    const float* x = (const float*)d_in[0];   // [8,16,512,512]
    const float* w = (const float*)d_in[1];   // [16,144]
    float* out = (float*)d_out;

    static int attr_done = 0;
    if (!attr_done) {
        cudaFuncSetAttribute(conv_mma_pipe,
                             cudaFuncAttributeMaxDynamicSharedMemorySize, SM_TOTAL);
        attr_done = 1;
    }
    conv_mma_pipe<<<GRID, 256, SM_TOTAL>>>(x, w, out);
}

// round 6
// speedup vs baseline: 4.7219x; 1.0949x over previous
#include <cuda_runtime.h>
#include <cuda_fp16.h>
#include <cstdint>

// Conv2D 3x3 s1 p1: x[8,16,512,512] fp32 * w[16,144] -> out[8,16,512,512]
// Implicit GEMM on mma.sync.m16n8k16 (f16, f32 acc), persistent CTAs, depth-1
// cp.async pipeline (16B interior + 4B halo), ldmatrix A-frags, half2 cvt,
// single fp16 tile buffer + 2 barriers -> 75.5KB smem -> 3 CTAs/SM.
// CTA tile: 32(x) x 16(y) pixels, all 16 co. 8 warps x 4 m16-tiles.

#define HW     512
#define NSX    34
#define NSY    18
#define CPAD   24        // ci stride (halves): 48B rows, LDSM conflict-free, 16B aligned
#define RAWROW 36        // raw row: [0..31]=interior gx x0..x0+31, [32]=x0-1, [33]=x0+32
#define NTILES 4096
#define GRID   456       // 3 CTAs/SM x 152 SMs

#define RAW_OFF 0                          // 16*18*36*4 = 41472 B
#define NS_OFF  41472                      // 18*34*24*2 = 29376 B
#define BS_OFF  (41472 + 29376)            // 70848
#define SM_TOTAL (70848 + 4608)            // 75456 B -> 3 CTAs/SM

static __device__ __forceinline__ void mma16816(float* c, uint32_t a0, uint32_t a1,
                                                uint32_t a2, uint32_t a3,
                                                uint32_t b0, uint32_t b1) {
    asm volatile(
        "mma.sync.aligned.m16n8k16.row.col.f32.f16.f16.f32 "
        "{%0,%1,%2,%3}, {%4,%5,%6,%7}, {%8,%9}, {%0,%1,%2,%3};"
        : "+f"(c[0]), "+f"(c[1]), "+f"(c[2]), "+f"(c[3])
        : "r"(a0), "r"(a1), "r"(a2), "r"(a3), "r"(b0), "r"(b1));
}

static __device__ __forceinline__ void ldsm4(uint32_t& a0, uint32_t& a1,
                                             uint32_t& a2, uint32_t& a3, uint32_t addr) {
    asm volatile("ldmatrix.sync.aligned.m8n8.x4.shared.b16 {%0,%1,%2,%3}, [%4];"
                 : "=r"(a0), "=r"(a1), "=r"(a2), "=r"(a3) : "r"(addr));
}

static __device__ __forceinline__ void cp16(uint32_t daddr, const float* src, uint32_t sz) {
    asm volatile("cp.async.cg.shared.global [%0], [%1], 16, %2;"
                 :: "r"(daddr), "l"(src), "r"(sz) : "memory");
}
static __device__ __forceinline__ void cp4(uint32_t daddr, const float* src, uint32_t sz) {
    asm volatile("cp.async.ca.shared.global [%0], [%1], 4, %2;"
                 :: "r"(daddr), "l"(src), "r"(sz) : "memory");
}

static __device__ __forceinline__ uint32_t smem_u32(const void* p) {
    uint32_t a;
    asm("{ .reg .u64 t; cvta.to.shared.u64 t, %1; cvt.u32.u64 %0, t; }" : "=r"(a) : "l"(p));
    return a;
}

// Issue all cp.async for one tile (per-thread share), then commit.
static __device__ __forceinline__ void issue_tile_cp(const float* __restrict__ xin,
                                                     uint32_t sraw, int tile,
                                                     int ci, int xb) {
    const int x0 = (tile & 15) * 32, y0 = ((tile >> 4) & 31) * 16, n = tile >> 9;
    const float* src = xin + (size_t)(n * 16 + ci) * HW * HW;
    const uint32_t dbase = sraw + (uint32_t)(ci * NSY * RAWROW) * 4;

    // interior: chunk c8 = xb&7 (16B), rows yy = 2j + (xb>>3), 9 rows
    const int c8 = xb & 7, yh = xb >> 3;
    #pragma unroll
    for (int j = 0; j < 9; ++j) {
        const int yy = 2 * j + yh;
        const int gy = y0 + yy - 1;
        const bool okY = (unsigned)gy < HW;
        const float* s = src + (size_t)(okY ? gy : 0) * HW + x0 + 4 * c8;
        cp16(dbase + (uint32_t)(yy * RAWROW + 4 * c8) * 4, s, okY ? 16u : 0u);
    }
    // halo: slots xb, xb+16, xb+32 (<36); slot -> (yy = slot>>1, side = slot&1)
    #pragma unroll
    for (int s2 = 0; s2 < 3; ++s2) {
        const int slot = xb + 16 * s2;
        if (slot < 2 * NSY) {
            const int yy = slot >> 1, side = slot & 1;
            const int gy = y0 + yy - 1;
            const int gx = side ? (x0 + 32) : (x0 - 1);
            const bool ok = ((unsigned)gy < HW) && ((unsigned)gx < HW);
            const float* s = src + (size_t)(ok ? gy : 0) * HW + (ok ? gx : 0);
            cp4(dbase + (uint32_t)(yy * RAWROW + 32 + side) * 4, s, ok ? 4u : 0u);
        }
    }
    asm volatile("cp.async.commit_group;" ::: "memory");
}

__global__ __launch_bounds__(256, 3)
void conv_mma_pipe(const float* __restrict__ xin,
                   const float* __restrict__ wgt,
                   float* __restrict__ out)
{
    extern __shared__ __align__(16) char smem[];
    float*  raw = (float*)(smem + RAW_OFF);
    __half* ns  = (__half*)(smem + NS_OFF);
    __half* Bs  = (__half*)(smem + BS_OFF);
    const uint32_t sraw = smem_u32(smem) + RAW_OFF;
    const uint32_t nsu  = smem_u32(smem) + NS_OFF;

    const int t    = threadIdx.x;
    const int lane = t & 31;
    const int wrp  = t >> 5;
    const int ci   = t >> 4;   // cp.async mapping
    const int xb   = t & 15;

    // ---- stage weights once: Bs[kh][co][kw*16+ci] ----
    #pragma unroll
    for (int r = 0; r < 9; ++r) {
        int idx = t + r * 256;
        int kh  = idx / 768;
        int rem = idx - kh * 768;
        int co  = rem / 48;
        int k   = rem - co * 48;
        Bs[idx] = __float2half_rn(wgt[co * 144 + (k & 15) * 9 + kh * 3 + (k >> 4)]);
    }

    const int g  = lane >> 2;
    const int cq = (lane & 3) * 2;
    // ldmatrix per-thread base: row = lane&15 (m), khalf = lane>>4
    const uint32_t fb = nsu + (uint32_t)(((lane & 15) * CPAD + (lane >> 4) * 8) * 2);

    // cvt mapping: cpair = wrp (ci pair), lane = ns x-column
    const float* cvt_r0 = raw + (2 * wrp) * (NSY * RAWROW);
    const float* cvt_r1 = cvt_r0 + NSY * RAWROW;
    const int scolA = (lane == 0) ? 32 : (lane - 1);           // ns xx = lane
    const int xxB   = 32 + lane;                               // ns xx = 32,33 (lane<2)
    const int scolB = (xxB == 33) ? 33 : (xxB - 1);

    issue_tile_cp(xin, sraw, blockIdx.x, ci, xb);

    for (int tile = blockIdx.x; tile < NTILES; tile += GRID) {
        const int x0 = (tile & 15) * 32, y0 = ((tile >> 4) & 31) * 16, n = tile >> 9;

        asm volatile("cp.async.wait_group 0;" ::: "memory");
        __syncthreads();   // raw ready for all; previous compute done (ns free)

        // ---- cvt raw fp32 -> ns fp16 (half2 over ci pairs) ----
        #pragma unroll 3
        for (int yy = 0; yy < NSY; ++yy) {
            const int ro = yy * RAWROW;
            __half2 h = __floats2half2_rn(cvt_r0[ro + scolA], cvt_r1[ro + scolA]);
            *(__half2*)&ns[(yy * NSX + lane) * CPAD + 2 * wrp] = h;
            if (lane < 2) {
                __half2 h2 = __floats2half2_rn(cvt_r0[ro + scolB], cvt_r1[ro + scolB]);
                *(__half2*)&ns[(yy * NSX + xxB) * CPAD + 2 * wrp] = h2;
            }
        }
        __syncthreads();   // ns visible; raw fully consumed

        // ---- prefetch next tile (overlaps compute) ----
        if (tile + GRID < NTILES)
            issue_tile_cp(xin, sraw, tile + GRID, ci, xb);

        // ---- compute ----
        float acc[4][2][4];
        #pragma unroll
        for (int i = 0; i < 4; ++i)
            #pragma unroll
            for (int nn = 0; nn < 2; ++nn)
                #pragma unroll
                for (int j = 0; j < 4; ++j) acc[i][nn][j] = 0.0f;

        #pragma unroll
        for (int dy = 0; dy < 3; ++dy) {
            uint32_t bf[3][2][2];
            #pragma unroll
            for (int kw = 0; kw < 3; ++kw)
                #pragma unroll
                for (int nn = 0; nn < 2; ++nn) {
                    const __half* bp = &Bs[(dy * 16 + nn * 8 + g) * 48 + kw * 16 + cq];
                    bf[kw][nn][0] = *(const uint32_t*)bp;
                    bf[kw][nn][1] = *(const uint32_t*)(bp + 8);
                }
            #pragma unroll
            for (int i = 0; i < 4; ++i) {
                const int m    = wrp * 4 + i;
                const int yloc = m >> 1;
                const int xh   = m & 1;
                const int yy   = yloc + dy;
                #pragma unroll
                for (int kw = 0; kw < 3; ++kw) {
                    uint32_t a0, a1, a2, a3;
                    ldsm4(a0, a1, a2, a3,
                          fb + (uint32_t)((yy * NSX + xh * 16 + kw) * (CPAD * 2)));
                    mma16816(acc[i][0], a0, a1, a2, a3, bf[kw][0][0], bf[kw][0][1]);
                    mma16816(acc[i][1], a0, a1, a2, a3, bf[kw][1][0], bf[kw][1][1]);
                }
            }
        }

        // ---- epilogue ----
        #pragma unroll
        for (int i = 0; i < 4; ++i) {
            const int m    = wrp * 4 + i;
            const int yloc = m >> 1;
            const int xh   = m & 1;
            const int y  = y0 + yloc;
            const int xg = x0 + xh * 16 + g;
            #pragma unroll
            for (int nn = 0; nn < 2; ++nn) {
                const int co = nn * 8 + cq;
                float* op = out + ((size_t)(n * 16 + co) * HW + y) * HW + xg;
                op[0]                   = acc[i][nn][0];
                op[(size_t)HW * HW]     = acc[i][nn][1];
                op[8]                   = acc[i][nn][2];
                op[(size_t)HW * HW + 8] = acc[i][nn][3];
            }
        }
    }
}

extern "C" void kernel_launch(void* const* d_in, const int* in_sizes, int n_in,
                              void* d_out, int out_size) {
    const float* x = (const float*)d_in[0];   // [8,16,512,512]
    const float* w = (const float*)d_in[1];   // [16,144]
    float* out = (float*)d_out;

    static int attr_done = 0;
    if (!attr_done) {
        cudaFuncSetAttribute(conv_mma_pipe,
                             cudaFuncAttributeMaxDynamicSharedMemorySize, SM_TOTAL);
        attr_done = 1;
    }
    conv_mma_pipe<<<GRID, 256, SM_TOTAL>>>(x, w, out);
}